// round 8
// baseline (speedup 1.0000x reference)
#include <cuda_runtime.h>

// YOLOv3 loss. Dense coalesced float4 stream with near-zero per-element ALU:
// TPB=256 == 1 (mod 15), so thread residue r=(cb+t)%15 is computed once and
// the k-th load's j%15 = (r+k)%15. po sits in float4 j iff j%15==1 (.x) or
// j%15==8 (.z) -> two select-accumulates per load, TWO softplus per thread.
// Winner/box/cls corrections handled sparsely; device state self-cleans via
// atomicExch so the kernel is graph-replay safe with no init pass.
//
//  pred_large  [64,3,13,13,30]   pred_medium [64,3,26,26,30]
//  pred_small  [64,3,52,52,30]   targets [2048,6]   out[4]={tot,box,obj,cls}

#define NC 25
#define CH 30
#define MAX_CELLS (64*3*(13*13 + 26*26 + 52*52))   // 681408
#define MAXT (3*2048)
#define TPB 256                   // must be == 1 (mod 15)
#define UNROLL 8
#define CHUNK (TPB * UNROLL)      // 2048 float4 per block

__constant__ float c_anc[9][2] = {
    {116.f,  90.f}, {156.f, 198.f}, {373.f, 326.f},   // grid 13
    { 30.f,  61.f}, { 62.f,  45.f}, { 59.f, 119.f},   // grid 26
    { 10.f,  13.f}, { 16.f,  30.f}, { 33.f,  23.f}};  // grid 52

__device__ int      g_winner[MAX_CELLS];   // 0 = empty; self-cleaning
__device__ unsigned g_clsmask[MAX_CELLS];
__device__ int      g_list[MAXT];

__device__ __forceinline__ float softplusf(float x) {
    return fmaxf(x, 0.0f) + log1pf(expf(-fabsf(x)));
}
__device__ __forceinline__ float bcef(float x, float t) {
    return softplusf(x) - t * x;
}

__global__ void scatter_kernel(const float* __restrict__ tgt, int N,
                               int off1, int off2, float* __restrict__ out) {
    int idx = blockIdx.x * blockDim.x + threadIdx.x;
    if (idx < 4) out[idx] = 0.0f;
    if (idx >= 3 * N) return;
    int s = idx / N;
    int n = idx - s * N;
    const float* T = tgt + 6 * n;
    int   gridi = (s == 0) ? 13 : (s == 1) ? 26 : 52;
    float gridf = (float)gridi;
    int   off   = (s == 0) ? 0  : (s == 1) ? off1 : off2;

    float txf = T[2] * gridf, tyf = T[3] * gridf;
    float twf = T[4] * gridf, thf = T[5] * gridf;
    int gx = (int)floorf(txf), gy = (int)floorf(tyf);

    int cell = -1;
    if (gx >= 0 && gx < gridi && gy >= 0 && gy < gridi) {
        int bi  = (int)T[0];
        int cid = (int)T[1];
        float best_iou = -1.0f; int best = 0;
        #pragma unroll
        for (int a = 0; a < 3; a++) {
            float saw = c_anc[s*3 + a][0] / gridf;
            float sah = c_anc[s*3 + a][1] / gridf;
            float inter = fminf(twf, saw) * fminf(thf, sah);
            float uni   = twf * thf + saw * sah - inter;
            float iou   = inter / (uni + 1e-9f);
            if (iou > best_iou) { best_iou = iou; best = a; }   // first-max (argmax)
        }
        cell = off + ((bi * 3 + best) * gridi + gy) * gridi + gx;
        atomicMax(&g_winner[cell], n + 1);        // last target index wins
        atomicOr(&g_clsmask[cell], 1u << cid);    // class union on collision
    }
    g_list[idx] = cell;
}

__global__ void __launch_bounds__(TPB)
main_kernel(const float* __restrict__ pl,
            const float* __restrict__ pm,
            const float* __restrict__ ps,
            const float* __restrict__ tgt,
            float* __restrict__ out,
            int off1, int off2,
            int b0, int b1,              // block counts for arrays 0,1
            int n0, int n1, int n2,      // float4 counts per array
            int nT) {
    int b = blockIdx.x, t = threadIdx.x;

    // ---- map block -> (array, float4 chunk) ----
    const float4* src; int nf4, cb;
    if (b < b0)           { src = (const float4*)pl; nf4 = n0; cb = b * CHUNK; }
    else if (b < b0 + b1) { src = (const float4*)pm; nf4 = n1; cb = (b - b0) * CHUNK; }
    else                  { src = (const float4*)ps; nf4 = n2; cb = (b - b0 - b1) * CHUNK; }

    float box = 0.0f, obj = 0.0f, cls = 0.0f;

    // ---- dense coalesced stream; po extraction via static residue trick ----
    {
        int j0 = cb + t;
        unsigned r  = (unsigned)j0 % 15u;        // one mod per thread
        int k1 = (int)((16u - r) % 15u);         // k with j%15==1 -> po = v.x
        int k8 = (int)((23u - r) % 15u);         // k with j%15==8 -> po = v.z
        float po1 = -100.0f, po2 = -100.0f;      // softplus(-100) == 0

        if (cb + CHUNK <= nf4) {                 // fast path: no bounds checks
            #pragma unroll
            for (int k = 0; k < UNROLL; k++) {
                float4 v = __ldcg(src + j0 + k * TPB);
                po1 = (k == k1) ? v.x : po1;
                po2 = (k == k8) ? v.z : po2;
            }
        } else {                                 // tail blocks (<=3 total)
            #pragma unroll
            for (int k = 0; k < UNROLL; k++) {
                int j = j0 + k * TPB;
                if (j < nf4) {
                    float4 v = __ldcg(src + j);
                    po1 = (k == k1) ? v.x : po1;
                    po2 = (k == k8) ? v.z : po2;
                }
            }
        }
        obj = 0.5f * (softplusf(po1) + softplusf(po2));
    }

    // ---- winner corrections on first nT global threads (self-cleaning) ----
    int gid = b * TPB + t;
    if (gid < nT) {
        int cell = g_list[gid];
        if (cell >= 0) {
            int w = atomicExch(&g_winner[cell], 0);       // claim + clean
            if (w > 0) {
                unsigned m = atomicExch(&g_clsmask[cell], 0u);
                int n = w - 1;
                const float* pp; int local; float gridf; int sc;
                if (cell < off1)      { pp = pl; local = cell;        gridf = 13.0f; sc = 0; }
                else if (cell < off2) { pp = pm; local = cell - off1; gridf = 26.0f; sc = 1; }
                else                  { pp = ps; local = cell - off2; gridf = 52.0f; sc = 2; }
                const float* P  = pp + (long long)local * CH;
                const float* Tg = tgt + 6 * n;

                float txf = Tg[2] * gridf, tyf = Tg[3] * gridf;
                float twf = Tg[4] * gridf, thf = Tg[5] * gridf;

                float best_iou = -1.0f, saw_b = 1.0f, sah_b = 1.0f;
                #pragma unroll
                for (int a = 0; a < 3; a++) {
                    float saw = c_anc[sc*3 + a][0] / gridf;
                    float sah = c_anc[sc*3 + a][1] / gridf;
                    float inter = fminf(twf, saw) * fminf(thf, sah);
                    float uni   = twf * thf + saw * sah - inter;
                    float iou   = inter / (uni + 1e-9f);
                    if (iou > best_iou) { best_iou = iou; saw_b = saw; sah_b = sah; }
                }
                float tx = txf - floorf(txf);
                float ty = tyf - floorf(tyf);
                float tw = logf(twf / saw_b + 1e-16f);
                float th = logf(thf / sah_b + 1e-16f);

                float px = P[0], py = P[1], pw = P[2], ph = P[3], po = P[4];
                float dw = pw - tw, dh = ph - th;
                box = 5.0f * (bcef(px, tx) + bcef(py, ty) + dw * dw + dh * dh);

                // winner obj: softplus(-po); base already contributed 0.5*softplus(po)
                obj += 0.5f * softplusf(po) - po;

                #pragma unroll
                for (int c = 0; c < NC; c++) {
                    float pc = P[5 + c];
                    cls += softplusf(pc) - (((m >> c) & 1u) ? pc : 0.0f);
                }
            }
        }
    }

    // ---- block reduction then 4 atomics per block ----
    #pragma unroll
    for (int o = 16; o > 0; o >>= 1) {
        box += __shfl_down_sync(0xFFFFFFFFu, box, o);
        obj += __shfl_down_sync(0xFFFFFFFFu, obj, o);
        cls += __shfl_down_sync(0xFFFFFFFFu, cls, o);
    }
    __shared__ float sb[8], so[8], sc2[8];
    int lane = t & 31, warp = t >> 5;
    if (lane == 0) { sb[warp] = box; so[warp] = obj; sc2[warp] = cls; }
    __syncthreads();
    if (warp == 0) {
        box = (lane < 8) ? sb[lane] : 0.0f;
        obj = (lane < 8) ? so[lane] : 0.0f;
        cls = (lane < 8) ? sc2[lane] : 0.0f;
        #pragma unroll
        for (int o = 4; o > 0; o >>= 1) {
            box += __shfl_down_sync(0xFFFFFFFFu, box, o);
            obj += __shfl_down_sync(0xFFFFFFFFu, obj, o);
            cls += __shfl_down_sync(0xFFFFFFFFu, cls, o);
        }
        if (lane == 0) {
            atomicAdd(out + 0, box + obj + cls);
            atomicAdd(out + 1, box);
            atomicAdd(out + 2, obj);
            atomicAdd(out + 3, cls);
        }
    }
}

extern "C" void kernel_launch(void* const* d_in, const int* in_sizes, int n_in,
                              void* d_out, int out_size) {
    const float* pl  = (const float*)d_in[0];
    const float* pm  = (const float*)d_in[1];
    const float* ps  = (const float*)d_in[2];
    const float* tgt = (const float*)d_in[3];
    float* out = (float*)d_out;

    int B = in_sizes[0] / (3 * 13 * 13 * CH);
    int N = in_sizes[3] / 6;
    int r0 = B * 3 * 13 * 13;
    int r1 = B * 3 * 26 * 26;
    int r2 = B * 3 * 52 * 52;
    int off1 = r0, off2 = r0 + r1;
    int nT = 3 * N;

    int n0 = r0 * CH / 4;          // float4 counts (rows*30 divisible by 4)
    int n1 = r1 * CH / 4;
    int n2 = r2 * CH / 4;
    int b0 = (n0 + CHUNK - 1) / CHUNK;
    int b1 = (n1 + CHUNK - 1) / CHUNK;
    int b2 = (n2 + CHUNK - 1) / CHUNK;

    scatter_kernel<<<(nT + 255) / 256, 256>>>(tgt, N, off1, off2, out);
    main_kernel<<<b0 + b1 + b2, TPB>>>(pl, pm, ps, tgt, out,
                                       off1, off2, b0, b1, n0, n1, n2, nT);
}

// round 9
// speedup vs baseline: 1.6803x; 1.6803x over previous
#include <cuda_runtime.h>

// YOLOv3 loss — single fused kernel.
// Blocks 0..nScat-1 scatter the 6144 (target,scale) pairs (winner = max target
// index via atomicMax, class union via atomicOr), signal via fenced counter,
// then everyone streams the po channel (R3 pattern: 8 strided scalar loads per
// thread, the wall-clock-fastest variant measured). Correction threads spin on
// the counter (scatter blocks are all in wave 1 -> no deadlock), claim winner
// cells with atomicExch (which also self-cleans state for graph replay), and
// add box/obj/cls corrections. Last block writes out[4] and resets globals.
//
//  pred_large  [64,3,13,13,30]   pred_medium [64,3,26,26,30]
//  pred_small  [64,3,52,52,30]   targets [2048,6]   out[4]={tot,box,obj,cls}
//
// obj = sum_all 0.5*softplus(po) + sum_winners (0.5*softplus(po) - po)

#define NC 25
#define CH 30
#define MAX_CELLS (64*3*(13*13 + 26*26 + 52*52))   // 681408
#define TPB 256
#define CPT 8

__constant__ float c_anc[9][2] = {
    {116.f,  90.f}, {156.f, 198.f}, {373.f, 326.f},   // grid 13
    { 30.f,  61.f}, { 62.f,  45.f}, { 59.f, 119.f},   // grid 26
    { 10.f,  13.f}, { 16.f,  30.f}, { 33.f,  23.f}};  // grid 52

__device__ int      g_winner[MAX_CELLS];   // 0 = empty; self-cleaning
__device__ unsigned g_clsmask[MAX_CELLS];
__device__ int      g_done  = 0;           // scatter blocks finished
__device__ int      g_pass  = 0;           // correction blocks finished
__device__ int      g_bdone = 0;           // reduction blocks finished
__device__ float    g_acc[3] = {0.f, 0.f, 0.f};

__device__ __forceinline__ float softplusf(float x) {
    return fmaxf(x, 0.0f) + log1pf(expf(-fabsf(x)));
}
__device__ __forceinline__ float bcef(float x, float t) {
    return softplusf(x) - t * x;
}

__global__ void __launch_bounds__(TPB)
fused_kernel(const float* __restrict__ pl,
             const float* __restrict__ pm,
             const float* __restrict__ ps,
             const float* __restrict__ tgt,
             float* __restrict__ out,
             int off1, int off2, int total, int N, int nT, int nScat) {
    int b = blockIdx.x, t = threadIdx.x;
    int gid = b * TPB + t;
    int T   = gridDim.x * TPB;

    float box = 0.0f, obj = 0.0f, cls = 0.0f;
    int   cell = -1;            // register handoff scatter -> correction

    // ================= phase 1: scatter (blocks 0..nScat-1) =================
    if (b < nScat) {
        if (gid < nT) {
            int s = gid / N;
            int n = gid - s * N;
            const float* Tg = tgt + 6 * n;
            int   gridi = (s == 0) ? 13 : (s == 1) ? 26 : 52;
            float gridf = (float)gridi;
            int   off   = (s == 0) ? 0  : (s == 1) ? off1 : off2;

            float txf = Tg[2] * gridf, tyf = Tg[3] * gridf;
            float twf = Tg[4] * gridf, thf = Tg[5] * gridf;
            int gx = (int)floorf(txf), gy = (int)floorf(tyf);

            if (gx >= 0 && gx < gridi && gy >= 0 && gy < gridi) {
                int bi  = (int)Tg[0];
                int cid = (int)Tg[1];
                float best_iou = -1.0f; int best = 0;
                #pragma unroll
                for (int a = 0; a < 3; a++) {
                    float saw = c_anc[s*3 + a][0] / gridf;
                    float sah = c_anc[s*3 + a][1] / gridf;
                    float inter = fminf(twf, saw) * fminf(thf, sah);
                    float uni   = twf * thf + saw * sah - inter;
                    float iou   = inter / (uni + 1e-9f);
                    if (iou > best_iou) { best_iou = iou; best = a; }  // first-max
                }
                cell = off + ((bi * 3 + best) * gridi + gy) * gridi + gx;
                atomicMax(&g_winner[cell], n + 1);     // last target index wins
                atomicOr(&g_clsmask[cell], 1u << cid); // class union
                __threadfence();                       // atomics before g_done
            }
        }
        __syncthreads();
        if (t == 0) atomicAdd(&g_done, 1);
    }

    // ================= phase 2: po base stream (all blocks) =================
    {
        float v[CPT];
        #pragma unroll
        for (int k = 0; k < CPT; k++) {
            int c = gid + k * T;
            float x = -100.0f;                 // softplus(-100) == 0
            if (c < total) {
                const float* p; int local;
                if (c < off1)      { p = pl; local = c; }
                else if (c < off2) { p = pm; local = c - off1; }
                else               { p = ps; local = c - off2; }
                x = __ldg(p + (long long)local * CH + 4);
            }
            v[k] = x;
        }
        #pragma unroll
        for (int k = 0; k < CPT; k++) obj += 0.5f * softplusf(v[k]);
    }

    // ============ phase 3: winner corrections (blocks 0..nScat-1) ===========
    if (b < nScat) {
        // all nScat blocks are in wave 1 (grid >> 148) -> spin is safe
        while (*(volatile int*)&g_done < nScat) {}
        __threadfence();

        if (cell >= 0) {
            int w = atomicExch(&g_winner[cell], 0);       // claim + clean
            if (w > 0) {
                unsigned m = atomicExch(&g_clsmask[cell], 0u);
                int n = w - 1;
                const float* pp; int local; float gridf; int sc;
                if (cell < off1)      { pp = pl; local = cell;        gridf = 13.0f; sc = 0; }
                else if (cell < off2) { pp = pm; local = cell - off1; gridf = 26.0f; sc = 1; }
                else                  { pp = ps; local = cell - off2; gridf = 52.0f; sc = 2; }
                const float* P  = pp + (long long)local * CH;
                const float* Tg = tgt + 6 * n;

                float txf = Tg[2] * gridf, tyf = Tg[3] * gridf;
                float twf = Tg[4] * gridf, thf = Tg[5] * gridf;

                float best_iou = -1.0f, saw_b = 1.0f, sah_b = 1.0f;
                #pragma unroll
                for (int a = 0; a < 3; a++) {
                    float saw = c_anc[sc*3 + a][0] / gridf;
                    float sah = c_anc[sc*3 + a][1] / gridf;
                    float inter = fminf(twf, saw) * fminf(thf, sah);
                    float uni   = twf * thf + saw * sah - inter;
                    float iou   = inter / (uni + 1e-9f);
                    if (iou > best_iou) { best_iou = iou; saw_b = saw; sah_b = sah; }
                }
                float tx = txf - floorf(txf);
                float ty = tyf - floorf(tyf);
                float tw = logf(twf / saw_b + 1e-16f);
                float th = logf(thf / sah_b + 1e-16f);

                float px = P[0], py = P[1], pw = P[2], ph = P[3], po = P[4];
                float dw = pw - tw, dh = ph - th;
                box = 5.0f * (bcef(px, tx) + bcef(py, ty) + dw * dw + dh * dh);

                obj += 0.5f * softplusf(po) - po;     // winner obj correction

                #pragma unroll
                for (int c = 0; c < NC; c++) {
                    float pc = P[5 + c];
                    cls += softplusf(pc) - (((m >> c) & 1u) ? pc : 0.0f);
                }
            }
        }
        __syncthreads();            // whole block past spin before reset
        if (t == 0) {
            int p = atomicAdd(&g_pass, 1);
            if (p == nScat - 1) { g_done = 0; g_pass = 0; __threadfence(); }
        }
    }

    // ================= phase 4: reduction + last-block output ===============
    #pragma unroll
    for (int o = 16; o > 0; o >>= 1) {
        box += __shfl_down_sync(0xFFFFFFFFu, box, o);
        obj += __shfl_down_sync(0xFFFFFFFFu, obj, o);
        cls += __shfl_down_sync(0xFFFFFFFFu, cls, o);
    }
    __shared__ float sb[8], so[8], sc2[8];
    int lane = t & 31, warp = t >> 5;
    if (lane == 0) { sb[warp] = box; so[warp] = obj; sc2[warp] = cls; }
    __syncthreads();
    if (warp == 0) {
        box = (lane < 8) ? sb[lane] : 0.0f;
        obj = (lane < 8) ? so[lane] : 0.0f;
        cls = (lane < 8) ? sc2[lane] : 0.0f;
        #pragma unroll
        for (int o = 4; o > 0; o >>= 1) {
            box += __shfl_down_sync(0xFFFFFFFFu, box, o);
            obj += __shfl_down_sync(0xFFFFFFFFu, obj, o);
            cls += __shfl_down_sync(0xFFFFFFFFu, cls, o);
        }
        if (lane == 0) {
            atomicAdd(&g_acc[0], box);
            atomicAdd(&g_acc[1], obj);
            atomicAdd(&g_acc[2], cls);
            __threadfence();
            int done = atomicAdd(&g_bdone, 1);
            if (done == gridDim.x - 1) {           // last block: publish + clean
                __threadfence();
                float bb = g_acc[0], oo = g_acc[1], cc = g_acc[2];
                out[0] = bb + oo + cc;
                out[1] = bb;
                out[2] = oo;
                out[3] = cc;
                g_acc[0] = 0.f; g_acc[1] = 0.f; g_acc[2] = 0.f;
                g_bdone = 0;
            }
        }
    }
}

extern "C" void kernel_launch(void* const* d_in, const int* in_sizes, int n_in,
                              void* d_out, int out_size) {
    const float* pl  = (const float*)d_in[0];
    const float* pm  = (const float*)d_in[1];
    const float* ps  = (const float*)d_in[2];
    const float* tgt = (const float*)d_in[3];
    float* out = (float*)d_out;

    int B = in_sizes[0] / (3 * 13 * 13 * CH);
    int N = in_sizes[3] / 6;
    int r0 = B * 3 * 13 * 13;
    int r1 = B * 3 * 26 * 26;
    int r2 = B * 3 * 52 * 52;
    int off1 = r0, off2 = r0 + r1;
    int total = off2 + r2;
    int nT = 3 * N;

    int threads = (total + CPT - 1) / CPT;
    int blocks  = (threads + TPB - 1) / TPB;          // 333 for B=64
    int nScat   = (nT + TPB - 1) / TPB;               // 24
    if (blocks < nScat) blocks = nScat;

    fused_kernel<<<blocks, TPB>>>(pl, pm, ps, tgt, out,
                                  off1, off2, total, N, nT, nScat);
}

// round 10
// speedup vs baseline: 1.6875x; 1.0043x over previous
#include <cuda_runtime.h>

// YOLOv3 loss — single fused kernel, wave-balanced (grid = 2*148), with
// winner corrections hoisted BEFORE the main stream so their scattered loads
// overlap with other blocks' streaming instead of extending the tail.
//
// Blocks 0..nScat-1: scatter (atomicMax winner = last target index wins,
// atomicOr class union), fenced counter signal, t0-only spin, corrections
// (atomicExch claim also self-cleans state for graph replay). All blocks then
// stream the po channel with 9 strided scalar loads/thread (128B line fill
// makes full-array DRAM traffic compulsory; strided keeps L2->SM tiny).
// Last block publishes out[4] and resets the accumulators.
//
//  pred_large  [64,3,13,13,30]   pred_medium [64,3,26,26,30]
//  pred_small  [64,3,52,52,30]   targets [2048,6]   out[4]={tot,box,obj,cls}
//
// obj = sum_all 0.5*softplus(po) + sum_winners (0.5*softplus(po) - po)

#define NC 25
#define CH 30
#define MAX_CELLS (64*3*(13*13 + 26*26 + 52*52))   // 681408
#define TPB 256
#define CPT 9

__constant__ float c_anc[9][2] = {
    {116.f,  90.f}, {156.f, 198.f}, {373.f, 326.f},   // grid 13
    { 30.f,  61.f}, { 62.f,  45.f}, { 59.f, 119.f},   // grid 26
    { 10.f,  13.f}, { 16.f,  30.f}, { 33.f,  23.f}};  // grid 52

__device__ int      g_winner[MAX_CELLS];   // 0 = empty; self-cleaning
__device__ unsigned g_clsmask[MAX_CELLS];
__device__ int      g_done  = 0;           // scatter blocks finished
__device__ int      g_pass  = 0;           // correction blocks finished
__device__ int      g_bdone = 0;           // reduction blocks finished
__device__ float    g_acc[3] = {0.f, 0.f, 0.f};

__device__ __forceinline__ float softplusf(float x) {
    return fmaxf(x, 0.0f) + log1pf(expf(-fabsf(x)));
}
__device__ __forceinline__ float bcef(float x, float t) {
    return softplusf(x) - t * x;
}

__global__ void __launch_bounds__(TPB)
fused_kernel(const float* __restrict__ pl,
             const float* __restrict__ pm,
             const float* __restrict__ ps,
             const float* __restrict__ tgt,
             float* __restrict__ out,
             int off1, int off2, int total, int N, int nT, int nScat) {
    int b = blockIdx.x, t = threadIdx.x;
    int gid = b * TPB + t;
    int T   = gridDim.x * TPB;

    float box = 0.0f, obj = 0.0f, cls = 0.0f;

    // ========== phase 1+2: scatter, sync, corrections (blocks 0..nScat-1) ====
    if (b < nScat) {
        int cell = -1;                        // register handoff
        if (gid < nT) {
            int s = gid / N;
            int n = gid - s * N;
            const float* Tg = tgt + 6 * n;
            int   gridi = (s == 0) ? 13 : (s == 1) ? 26 : 52;
            float gridf = (float)gridi;
            int   off   = (s == 0) ? 0  : (s == 1) ? off1 : off2;

            float txf = Tg[2] * gridf, tyf = Tg[3] * gridf;
            float twf = Tg[4] * gridf, thf = Tg[5] * gridf;
            int gx = (int)floorf(txf), gy = (int)floorf(tyf);

            if (gx >= 0 && gx < gridi && gy >= 0 && gy < gridi) {
                int bi  = (int)Tg[0];
                int cid = (int)Tg[1];
                float best_iou = -1.0f; int best = 0;
                #pragma unroll
                for (int a = 0; a < 3; a++) {
                    float saw = c_anc[s*3 + a][0] / gridf;
                    float sah = c_anc[s*3 + a][1] / gridf;
                    float inter = fminf(twf, saw) * fminf(thf, sah);
                    float uni   = twf * thf + saw * sah - inter;
                    float iou   = inter / (uni + 1e-9f);
                    if (iou > best_iou) { best_iou = iou; best = a; }  // first-max
                }
                cell = off + ((bi * 3 + best) * gridi + gy) * gridi + gx;
                atomicMax(&g_winner[cell], n + 1);     // last target index wins
                atomicOr(&g_clsmask[cell], 1u << cid); // class union
                __threadfence();                       // atomics before g_done
            }
        }
        __syncthreads();
        if (t == 0) {
            atomicAdd(&g_done, 1);
            // all nScat blocks are in wave 1 (nScat << 148) -> spin is safe
            while (*(volatile int*)&g_done < nScat) {}
        }
        __syncthreads();
        __threadfence();

        if (cell >= 0) {
            int w = atomicExch(&g_winner[cell], 0);       // claim + clean
            if (w > 0) {
                unsigned m = atomicExch(&g_clsmask[cell], 0u);
                int n = w - 1;
                const float* pp; int local; float gridf; int sc;
                if (cell < off1)      { pp = pl; local = cell;        gridf = 13.0f; sc = 0; }
                else if (cell < off2) { pp = pm; local = cell - off1; gridf = 26.0f; sc = 1; }
                else                  { pp = ps; local = cell - off2; gridf = 52.0f; sc = 2; }
                const float* P  = pp + (long long)local * CH;
                const float* Tg = tgt + 6 * n;

                float txf = Tg[2] * gridf, tyf = Tg[3] * gridf;
                float twf = Tg[4] * gridf, thf = Tg[5] * gridf;

                float best_iou = -1.0f, saw_b = 1.0f, sah_b = 1.0f;
                #pragma unroll
                for (int a = 0; a < 3; a++) {
                    float saw = c_anc[sc*3 + a][0] / gridf;
                    float sah = c_anc[sc*3 + a][1] / gridf;
                    float inter = fminf(twf, saw) * fminf(thf, sah);
                    float uni   = twf * thf + saw * sah - inter;
                    float iou   = inter / (uni + 1e-9f);
                    if (iou > best_iou) { best_iou = iou; saw_b = saw; sah_b = sah; }
                }
                float tx = txf - floorf(txf);
                float ty = tyf - floorf(tyf);
                float tw = logf(twf / saw_b + 1e-16f);
                float th = logf(thf / sah_b + 1e-16f);

                float px = P[0], py = P[1], pw = P[2], ph = P[3], po = P[4];
                float dw = pw - tw, dh = ph - th;
                box = 5.0f * (bcef(px, tx) + bcef(py, ty) + dw * dw + dh * dh);

                obj += 0.5f * softplusf(po) - po;     // winner obj correction

                #pragma unroll
                for (int c = 0; c < NC; c++) {
                    float pc = P[5 + c];
                    cls += softplusf(pc) - (((m >> c) & 1u) ? pc : 0.0f);
                }
            }
        }
        __syncthreads();            // whole block past spin before reset
        if (t == 0) {
            int p = atomicAdd(&g_pass, 1);
            if (p == nScat - 1) { g_done = 0; g_pass = 0; __threadfence(); }
        }
    }

    // ================= phase 3: po base stream (all blocks) =================
    {
        float v[CPT];
        #pragma unroll
        for (int k = 0; k < CPT; k++) {
            int c = gid + k * T;
            float x = -100.0f;                 // softplus(-100) == 0
            if (c < total) {
                const float* p; int local;
                if (c < off1)      { p = pl; local = c; }
                else if (c < off2) { p = pm; local = c - off1; }
                else               { p = ps; local = c - off2; }
                x = __ldg(p + (long long)local * CH + 4);
            }
            v[k] = x;
        }
        #pragma unroll
        for (int k = 0; k < CPT; k++) obj += 0.5f * softplusf(v[k]);
    }

    // ================= phase 4: reduction + last-block output ===============
    #pragma unroll
    for (int o = 16; o > 0; o >>= 1) {
        box += __shfl_down_sync(0xFFFFFFFFu, box, o);
        obj += __shfl_down_sync(0xFFFFFFFFu, obj, o);
        cls += __shfl_down_sync(0xFFFFFFFFu, cls, o);
    }
    __shared__ float sb[8], so[8], sc2[8];
    int lane = t & 31, warp = t >> 5;
    if (lane == 0) { sb[warp] = box; so[warp] = obj; sc2[warp] = cls; }
    __syncthreads();
    if (warp == 0) {
        box = (lane < 8) ? sb[lane] : 0.0f;
        obj = (lane < 8) ? so[lane] : 0.0f;
        cls = (lane < 8) ? sc2[lane] : 0.0f;
        #pragma unroll
        for (int o = 4; o > 0; o >>= 1) {
            box += __shfl_down_sync(0xFFFFFFFFu, box, o);
            obj += __shfl_down_sync(0xFFFFFFFFu, obj, o);
            cls += __shfl_down_sync(0xFFFFFFFFu, cls, o);
        }
        if (lane == 0) {
            atomicAdd(&g_acc[0], box);
            atomicAdd(&g_acc[1], obj);
            atomicAdd(&g_acc[2], cls);
            __threadfence();
            int done = atomicAdd(&g_bdone, 1);
            if (done == gridDim.x - 1) {           // last block: publish + clean
                __threadfence();
                float bb = g_acc[0], oo = g_acc[1], cc = g_acc[2];
                out[0] = bb + oo + cc;
                out[1] = bb;
                out[2] = oo;
                out[3] = cc;
                g_acc[0] = 0.f; g_acc[1] = 0.f; g_acc[2] = 0.f;
                g_bdone = 0;
            }
        }
    }
}

extern "C" void kernel_launch(void* const* d_in, const int* in_sizes, int n_in,
                              void* d_out, int out_size) {
    const float* pl  = (const float*)d_in[0];
    const float* pm  = (const float*)d_in[1];
    const float* ps  = (const float*)d_in[2];
    const float* tgt = (const float*)d_in[3];
    float* out = (float*)d_out;

    int B = in_sizes[0] / (3 * 13 * 13 * CH);
    int N = in_sizes[3] / 6;
    int r0 = B * 3 * 13 * 13;
    int r1 = B * 3 * 26 * 26;
    int r2 = B * 3 * 52 * 52;
    int off1 = r0, off2 = r0 + r1;
    int total = off2 + r2;
    int nT = 3 * N;

    int threads = (total + CPT - 1) / CPT;            // 75712 for B=64
    int blocks  = (threads + TPB - 1) / TPB;          // 296 = 2 * 148 SMs
    int nScat   = (nT + TPB - 1) / TPB;               // 24
    if (blocks < nScat) blocks = nScat;

    fused_kernel<<<blocks, TPB>>>(pl, pm, ps, tgt, out,
                                  off1, off2, total, N, nT, nScat);
}